// round 1
// baseline (speedup 1.0000x reference)
#include <cuda_runtime.h>
#include <cuda_bf16.h>
#include <cstdint>

// Problem constants (fixed shapes for this problem instance)
#define BATCH   16
#define MAXLEN  384
#define HIDDEN  128
#define T_END   100.0f
#define N_MC    15
#define EPS_F   1e-10f

// Table config
#define G_TABLE 8192
#define NPTS    32                        // grid points per build block
#define H_STEP  (100.0f / (G_TABLE - 1))
#define INV_H   ((G_TABLE - 1) / 100.0f)

// MC RNG layout: u has 15*16*384 = 92160 elements; threefry counter split at half
#define MC_TOTAL 92160
#define MC_HALF  46080

// ---------------------------------------------------------------------------
// Device scratch (no allocations allowed)
// ---------------------------------------------------------------------------
__device__ float2 g_table[G_TABLE];       // (f, f') at grid points
__device__ double g_accum[2];             // [0] = sum_log, [1] = mc raw sum

// ---------------------------------------------------------------------------
// Table build: evaluate MLP value + derivative on grid, fp32.
// Block = 128 threads (4 warps), 32 grid points. Warp q computes outputs
// k in [32q, 32q+32); lane p = point. Activations in smem [j][p] as float2(v,d).
// Single buffer: outputs staged in registers, written back after barrier.
// ---------------------------------------------------------------------------
__global__ void build_table_kernel(
    const float* __restrict__ W1, const float* __restrict__ b1,
    const float* __restrict__ W2, const float* __restrict__ b2,
    const float* __restrict__ W3, const float* __restrict__ b3,
    const float* __restrict__ W4, const float* __restrict__ b4)
{
    __shared__ float2 buf[HIDDEN * NPTS];   // [j][p], 32 KB

    const int lane = threadIdx.x & 31;
    const int q    = threadIdx.x >> 5;      // warp id 0..3
    const int p    = lane;                  // point index within block
    const int gbase = blockIdx.x * NPTS;
    const float x = (float)(gbase + p) * H_STEP;

    // Zero accumulators for this graph replay (consumed by later kernels only)
    if (blockIdx.x == 0 && threadIdx.x == 0) {
        g_accum[0] = 0.0;
        g_accum[1] = 0.0;
    }

    // ---- Layer 1: h1[j] = tanh(W1[j]*x + b1[j]);  dh1[j] = (1-h1^2)*W1[j]
    #pragma unroll 4
    for (int jj = 0; jj < 32; ++jj) {
        int j = q * 32 + jj;
        float w = __ldg(&W1[j]);
        float v = tanhf(w * x + __ldg(&b1[j]));
        float d = (1.0f - v * v) * w;
        buf[j * NPTS + p] = make_float2(v, d);
    }
    __syncthreads();

    // ---- Layers 2 and 3
    const float* Ws[2] = { W2, W3 };
    const float* bs[2] = { b2, b3 };

    #pragma unroll 1
    for (int layer = 0; layer < 2; ++layer) {
        const float* __restrict__ W = Ws[layer];
        const float* __restrict__ bv = bs[layer];

        float rv[32], rd[32];               // staged outputs for this warp's k-range

        #pragma unroll 1
        for (int kc = 0; kc < 4; ++kc) {
            const int k0 = q * 32 + kc * 8;
            float accv[8], accd[8];
            #pragma unroll
            for (int r = 0; r < 8; ++r) { accv[r] = __ldg(&bv[k0 + r]); accd[r] = 0.0f; }

            #pragma unroll 4
            for (int j = 0; j < HIDDEN; ++j) {
                float2 h = buf[j * NPTS + p];
                const float4* wrow = reinterpret_cast<const float4*>(W + j * HIDDEN + k0);
                float4 w0 = __ldg(wrow);
                float4 w1 = __ldg(wrow + 1);
                float wv[8] = { w0.x, w0.y, w0.z, w0.w, w1.x, w1.y, w1.z, w1.w };
                #pragma unroll
                for (int r = 0; r < 8; ++r) {
                    accv[r] += wv[r] * h.x;
                    accd[r] += wv[r] * h.y;
                }
            }
            #pragma unroll
            for (int r = 0; r < 8; ++r) {
                float v = tanhf(accv[r]);
                rv[kc * 8 + r] = v;
                rd[kc * 8 + r] = (1.0f - v * v) * accd[r];
            }
        }
        __syncthreads();
        #pragma unroll 4
        for (int kk = 0; kk < 32; ++kk) {
            buf[(q * 32 + kk) * NPTS + p] = make_float2(rv[kk], rd[kk]);
        }
        __syncthreads();
    }

    // ---- Layer 4 + softplus head (warp 0 handles all 32 points; lane = point)
    if (q == 0) {
        float accv = __ldg(&b4[0]);
        float accd = 0.0f;
        #pragma unroll 4
        for (int j = 0; j < HIDDEN; ++j) {
            float w = __ldg(&W4[j]);
            float2 h = buf[j * NPTS + p];
            accv += w * h.x;
            accd += w * h.y;
        }
        float z = accv;
        // softplus: log1p(exp(-|z|)) + max(z, 0)
        float f = log1pf(expf(-fabsf(z))) + fmaxf(z, 0.0f);
        float sig = 1.0f / (1.0f + expf(-z));
        g_table[gbase + p] = make_float2(f, sig * accd);
    }
}

// ---------------------------------------------------------------------------
// Cubic Hermite interpolation from (value, derivative) table
// ---------------------------------------------------------------------------
__device__ __forceinline__ float table_interp(float x)
{
    float pf = x * INV_H;
    pf = fminf(fmaxf(pf, 0.0f), (float)(G_TABLE - 1));
    int g = (int)pf;
    if (g > G_TABLE - 2) g = G_TABLE - 2;
    float u = pf - (float)g;

    float2 a = __ldg(&g_table[g]);
    float2 b = __ldg(&g_table[g + 1]);

    float u2 = u * u;
    float u3 = u2 * u;
    float h00 = 2.0f * u3 - 3.0f * u2 + 1.0f;
    float h10 = u3 - 2.0f * u2 + u;
    float h01 = -2.0f * u3 + 3.0f * u2;
    float h11 = u3 - u2;
    return h00 * a.x + (h10 * H_STEP) * a.y + h01 * b.x + (h11 * H_STEP) * b.y;
}

// ---------------------------------------------------------------------------
// Pairs kernel: sum over valid events i of log(bg + sum_{j<i} f(t_i - t_j))
// grid = (BATCH, SPLIT), block = 256 (8 warps). Warp handles events i strided.
// ---------------------------------------------------------------------------
__global__ void pairs_kernel(const float* __restrict__ seq_pads,
                             const int* __restrict__ seq_lens,
                             const float* __restrict__ bg_ptr)
{
    const int b = blockIdx.x;
    __shared__ float ts[MAXLEN];
    __shared__ double wsum[8];

    const int len = __ldg(&seq_lens[b]);
    const float bg = __ldg(&bg_ptr[0]);

    for (int l = threadIdx.x; l < MAXLEN; l += blockDim.x)
        ts[l] = seq_pads[b * MAXLEN + l];
    __syncthreads();

    const int lane = threadIdx.x & 31;
    const int w    = threadIdx.x >> 5;
    const int nw   = blockDim.x >> 5;                  // 8
    const int wstride = gridDim.y * nw;                // total warps per batch
    double local = 0.0;

    for (int i = blockIdx.y * nw + w; i < len; i += wstride) {
        const float ti = ts[i];
        float s = 0.0f;
        for (int j = lane; j < i; j += 32)
            s += table_interp(ti - ts[j]);
        // warp reduction
        #pragma unroll
        for (int o = 16; o > 0; o >>= 1)
            s += __shfl_down_sync(0xffffffffu, s, o);
        if (lane == 0)
            local += (double)logf(bg + s);
    }

    if (lane == 0) wsum[w] = local;
    __syncthreads();
    if (threadIdx.x == 0) {
        double t = 0.0;
        #pragma unroll
        for (int k = 0; k < 8; ++k) t += wsum[k];
        atomicAdd(&g_accum[0], t);
    }
}

// ---------------------------------------------------------------------------
// Threefry-2x32 (JAX-compatible), key = (0, 42)
// ---------------------------------------------------------------------------
__device__ __forceinline__ uint32_t rotl32(uint32_t v, int s)
{
    return __funnelshift_l(v, v, s);
}

__device__ __forceinline__ void tf_round4(uint32_t& x0, uint32_t& x1,
                                          int a, int b, int c, int d)
{
    x0 += x1; x1 = rotl32(x1, a); x1 ^= x0;
    x0 += x1; x1 = rotl32(x1, b); x1 ^= x0;
    x0 += x1; x1 = rotl32(x1, c); x1 ^= x0;
    x0 += x1; x1 = rotl32(x1, d); x1 ^= x0;
}

__device__ __forceinline__ void threefry2x32_key0_42(uint32_t& x0, uint32_t& x1)
{
    const uint32_t ks0 = 0u;
    const uint32_t ks1 = 42u;
    const uint32_t ks2 = 0x1BD11BDAu ^ 42u;
    x0 += ks0; x1 += ks1;
    tf_round4(x0, x1, 13, 15, 26, 6);
    x0 += ks1; x1 += ks2 + 1u;
    tf_round4(x0, x1, 17, 29, 16, 24);
    x0 += ks2; x1 += ks0 + 2u;
    tf_round4(x0, x1, 13, 15, 26, 6);
    x0 += ks0; x1 += ks1 + 3u;
    tf_round4(x0, x1, 17, 29, 16, 24);
    x0 += ks1; x1 += ks2 + 4u;
    tf_round4(x0, x1, 13, 15, 26, 6);
    x0 += ks2; x1 += ks0 + 5u;
}

__device__ __forceinline__ float mc_contrib(int flat, uint32_t bits,
                                            const float* __restrict__ seq,
                                            const int* __restrict__ lens)
{
    const int l = flat % MAXLEN;
    const int b = (flat / MAXLEN) % BATCH;
    if (l >= __ldg(&lens[b])) return 0.0f;   // diff_last == 0 -> zero contribution
    // JAX uniform float32 conversion: bitcast(bits>>9 | 0x3f800000) - 1
    float u = __uint_as_float((bits >> 9) | 0x3f800000u) - 1.0f;
    float t = __ldg(&seq[b * MAXLEN + l]);
    float diff = T_END - t;
    float f = table_interp(u * diff);
    return (f + EPS_F) * diff;
}

// One thread per threefry counter pair: serves flat indices idx and idx+MC_HALF
__global__ void mc_kernel(const float* __restrict__ seq_pads,
                          const int* __restrict__ seq_lens)
{
    const int idx = blockIdx.x * blockDim.x + threadIdx.x;
    float contrib = 0.0f;
    if (idx < MC_HALF) {
        uint32_t x0 = (uint32_t)idx;
        uint32_t x1 = (uint32_t)(idx + MC_HALF);
        threefry2x32_key0_42(x0, x1);
        contrib  = mc_contrib(idx,           x0, seq_pads, seq_lens);
        contrib += mc_contrib(idx + MC_HALF, x1, seq_pads, seq_lens);
    }
    // warp reduce, then one double atomic per warp
    #pragma unroll
    for (int o = 16; o > 0; o >>= 1)
        contrib += __shfl_down_sync(0xffffffffu, contrib, o);
    if ((threadIdx.x & 31) == 0 && contrib != 0.0f)
        atomicAdd(&g_accum[1], (double)contrib);
}

// ---------------------------------------------------------------------------
// Finalize: nll = -(sum_log - (mc_sum/15 + B*T_END*bg)) / B
// ---------------------------------------------------------------------------
__global__ void finalize_kernel(const float* __restrict__ bg_ptr,
                                float* __restrict__ out)
{
    double bg = (double)__ldg(&bg_ptr[0]);
    double lamb_ints = g_accum[1] / (double)N_MC
                     + (double)BATCH * (double)T_END * bg;
    double nll = -(g_accum[0] - lamb_ints) / (double)BATCH;
    out[0] = (float)nll;
}

// ---------------------------------------------------------------------------
// Launch
// ---------------------------------------------------------------------------
extern "C" void kernel_launch(void* const* d_in, const int* in_sizes, int n_in,
                              void* d_out, int out_size)
{
    const float* seq  = (const float*)d_in[0];   // [16,384,1]
    const int*   lens = (const int*)  d_in[1];   // [16]
    const float* bg   = (const float*)d_in[2];   // [1]
    const float* W1   = (const float*)d_in[3];   // [1,128]
    const float* b1   = (const float*)d_in[4];
    const float* W2   = (const float*)d_in[5];   // [128,128] row-major [in][out]
    const float* b2   = (const float*)d_in[6];
    const float* W3   = (const float*)d_in[7];
    const float* b3   = (const float*)d_in[8];
    const float* W4   = (const float*)d_in[9];   // [128,1]
    const float* b4   = (const float*)d_in[10];
    float* out = (float*)d_out;

    (void)in_sizes; (void)n_in; (void)out_size;

    // 1) Build f / f' table (also zeroes accumulators for this replay)
    build_table_kernel<<<G_TABLE / NPTS, 128>>>(W1, b1, W2, b2, W3, b3, W4, b4);

    // 2) Pair-sum term: sum of log-intensities at valid events
    pairs_kernel<<<dim3(BATCH, 8), 256>>>(seq, lens, bg);

    // 3) Monte-Carlo integral term (exact JAX threefry reproduction)
    mc_kernel<<<(MC_HALF + 255) / 256, 256>>>(seq, lens);

    // 4) Combine
    finalize_kernel<<<1, 1>>>(bg, out);
}

// round 9
// speedup vs baseline: 1.4522x; 1.4522x over previous
#include <cuda_runtime.h>
#include <cuda_bf16.h>
#include <cstdint>

// Problem constants
#define BATCH   16
#define MAXLEN  384
#define HIDDEN  128
#define T_END   100.0f
#define N_MC    15
#define EPS_F   1e-10f

// Table config: value-only table, 4-point Lagrange interpolation.
// Interior grid: G_TABLE points covering [0,100]; one guard point each end.
// Packed as overlapping float4 windows: g_tab4[i] = {f_ext[i..i+3]}.
#define G_TABLE 4096
#define H_STEP  (100.0f / (float)(G_TABLE - 1))
#define INV_H   ((float)(G_TABLE - 1) / 100.0f)
#define G_EXT   (G_TABLE + 2)                  // ext index i -> x = (i-1)*H_STEP
#define G_TAB4  (G_TABLE - 1)                  // valid window starts: 0..G_TABLE-2

// MC RNG layout: 15*16*384 = 92160 uniforms; threefry counter split at half
#define MC_TOTAL 92160
#define MC_HALF  46080

// Fused consume kernel block layout
#define NB_PAIR 128                            // 16 batches x 8 slices
#define NB_MC   45                             // 45*256 threads * 4 counters = 46080
#define NB_ALL  (NB_PAIR + NB_MC)

// ---------------------------------------------------------------------------
// Device scratch (no allocations allowed)
// ---------------------------------------------------------------------------
__device__ float4       g_tab4[G_TAB4];        // overlapping 4-point windows
__device__ double       g_accum[2];            // [0]=sum_log, [1]=mc raw sum
__device__ unsigned int g_arrive;              // arrival ticket (reset by finalizer)

// ---------------------------------------------------------------------------
// Table build: evaluate MLP value on extended grid, fp32.
// Block = 256 threads (8 warps), 32 grid points (lane = point).
// Warp q computes hidden units k in [16q, 16q+16). Activations in smem [j][p].
// Head warp scatter-writes each value into its 4 overlapping float4 windows.
// ---------------------------------------------------------------------------
__global__ __launch_bounds__(256) void build_table_kernel(
    const float* __restrict__ W1, const float* __restrict__ b1,
    const float* __restrict__ W2, const float* __restrict__ b2,
    const float* __restrict__ W3, const float* __restrict__ b3,
    const float* __restrict__ W4, const float* __restrict__ b4)
{
    __shared__ float buf[HIDDEN * 32];          // [j][p], 16 KB
    __shared__ float part[8][33];               // head partial sums

    const int lane  = threadIdx.x & 31;
    const int q     = threadIdx.x >> 5;         // warp id 0..7
    const int p     = lane;                     // point index in block
    const int gbase = blockIdx.x * 32;
    const float x   = (float)(gbase + p - 1) * H_STEP;   // ext index -> x

    if (blockIdx.x == 0 && threadIdx.x == 0) {
        g_accum[0] = 0.0;
        g_accum[1] = 0.0;
    }

    // ---- Layer 1
    #pragma unroll
    for (int jj = 0; jj < 16; ++jj) {
        int j = q * 16 + jj;
        float w = __ldg(&W1[j]);
        buf[j * 32 + p] = tanhf(w * x + __ldg(&b1[j]));
    }
    __syncthreads();

    // ---- Layers 2, 3
    const float* Ws[2] = { W2, W3 };
    const float* bs[2] = { b2, b3 };

    #pragma unroll 1
    for (int layer = 0; layer < 2; ++layer) {
        const float* __restrict__ W  = Ws[layer];
        const float* __restrict__ bv = bs[layer];
        float rv[16];

        #pragma unroll
        for (int kc = 0; kc < 2; ++kc) {
            const int k0 = q * 16 + kc * 8;
            float acc[8];
            #pragma unroll
            for (int r = 0; r < 8; ++r) acc[r] = __ldg(&bv[k0 + r]);

            #pragma unroll 4
            for (int j = 0; j < HIDDEN; ++j) {
                float h = buf[j * 32 + p];
                const float4* wrow = reinterpret_cast<const float4*>(W + j * HIDDEN + k0);
                float4 w0 = __ldg(wrow);
                float4 w1 = __ldg(wrow + 1);
                acc[0] += w0.x * h; acc[1] += w0.y * h;
                acc[2] += w0.z * h; acc[3] += w0.w * h;
                acc[4] += w1.x * h; acc[5] += w1.y * h;
                acc[6] += w1.z * h; acc[7] += w1.w * h;
            }
            #pragma unroll
            for (int r = 0; r < 8; ++r) rv[kc * 8 + r] = tanhf(acc[r]);
        }
        __syncthreads();
        #pragma unroll
        for (int kk = 0; kk < 16; ++kk)
            buf[(q * 16 + kk) * 32 + p] = rv[kk];
        __syncthreads();
    }

    // ---- Layer 4 + softplus head: warp q sums j in [16q, 16q+16)
    {
        float accv = 0.0f;
        #pragma unroll
        for (int jj = 0; jj < 16; ++jj) {
            int j = q * 16 + jj;
            accv += __ldg(&W4[j]) * buf[j * 32 + p];
        }
        part[q][p] = accv;
    }
    __syncthreads();
    if (q == 0) {
        float z = __ldg(&b4[0]);
        #pragma unroll
        for (int k = 0; k < 8; ++k) z += part[k][p];
        float f = log1pf(expf(-fabsf(z))) + fmaxf(z, 0.0f);   // softplus
        int gi = gbase + p;                                   // ext index
        if (gi < G_EXT) {
            // f = f_ext[gi] belongs to window idx = gi - c at component c
            float* tabf = reinterpret_cast<float*>(g_tab4);
            #pragma unroll
            for (int c = 0; c < 4; ++c) {
                int idx = gi - c;
                if (idx >= 0 && idx < G_TAB4)
                    tabf[idx * 4 + c] = f;
            }
        }
    }
}

// ---------------------------------------------------------------------------
// 4-point cubic Lagrange interpolation, single LDG.128 per lookup
// ---------------------------------------------------------------------------
__device__ __forceinline__ float table_interp(float x)
{
    float pf = x * INV_H;
    pf = fminf(fmaxf(pf, 0.0f), (float)(G_TABLE - 1));
    int g = (int)pf;
    if (g > G_TABLE - 2) g = G_TABLE - 2;
    float u = pf - (float)g;

    float4 f = __ldg(&g_tab4[g]);

    float um1 = u - 1.0f, um2 = u - 2.0f, up1 = u + 1.0f;
    float w0 = -u  * um1 * um2 * (1.0f / 6.0f);
    float w1 = up1 * um1 * um2 * 0.5f;
    float w2 = -up1 * u  * um2 * 0.5f;
    float w3 = up1 * u  * um1 * (1.0f / 6.0f);
    return w0 * f.x + w1 * f.y + w2 * f.z + w3 * f.w;
}

// ---------------------------------------------------------------------------
// Threefry-2x32 (JAX-compatible), key = (0, 42)
// ---------------------------------------------------------------------------
__device__ __forceinline__ uint32_t rotl32(uint32_t v, int s)
{
    return __funnelshift_l(v, v, s);
}

__device__ __forceinline__ void tf_round4(uint32_t& x0, uint32_t& x1,
                                          int a, int b, int c, int d)
{
    x0 += x1; x1 = rotl32(x1, a); x1 ^= x0;
    x0 += x1; x1 = rotl32(x1, b); x1 ^= x0;
    x0 += x1; x1 = rotl32(x1, c); x1 ^= x0;
    x0 += x1; x1 = rotl32(x1, d); x1 ^= x0;
}

__device__ __forceinline__ void threefry2x32_key0_42(uint32_t& x0, uint32_t& x1)
{
    const uint32_t ks0 = 0u;
    const uint32_t ks1 = 42u;
    const uint32_t ks2 = 0x1BD11BDAu ^ 42u;
    x0 += ks0; x1 += ks1;
    tf_round4(x0, x1, 13, 15, 26, 6);
    x0 += ks1; x1 += ks2 + 1u;
    tf_round4(x0, x1, 17, 29, 16, 24);
    x0 += ks2; x1 += ks0 + 2u;
    tf_round4(x0, x1, 13, 15, 26, 6);
    x0 += ks0; x1 += ks1 + 3u;
    tf_round4(x0, x1, 17, 29, 16, 24);
    x0 += ks1; x1 += ks2 + 4u;
    tf_round4(x0, x1, 13, 15, 26, 6);
    x0 += ks2; x1 += ks0 + 5u;
}

__device__ __forceinline__ float mc_contrib(int flat, uint32_t bits,
                                            const float* __restrict__ seq,
                                            const int* __restrict__ lens)
{
    const int l = flat % MAXLEN;
    const int b = (flat / MAXLEN) % BATCH;
    if (l >= __ldg(&lens[b])) return 0.0f;       // diff_last == 0
    float u = __uint_as_float((bits >> 9) | 0x3f800000u) - 1.0f;
    float t = __ldg(&seq[b * MAXLEN + l]);
    float diff = T_END - t;
    float f = table_interp(u * diff);
    return (f + EPS_F) * diff;
}

// ---------------------------------------------------------------------------
// Fused consume kernel:
//   blocks [0, NB_PAIR): pair-sum log term for batch b = blk>>3, slice blk&7
//   blocks [NB_PAIR, NB_ALL): Monte-Carlo integral term
//   last-arriving block writes the final NLL.
// ---------------------------------------------------------------------------
__global__ __launch_bounds__(256) void consume_kernel(
    const float* __restrict__ seq_pads,
    const int*   __restrict__ seq_lens,
    const float* __restrict__ bg_ptr,
    float*       __restrict__ out)
{
    __shared__ float  ts[MAXLEN];
    __shared__ double wsum[8];

    const int lane = threadIdx.x & 31;
    const int w    = threadIdx.x >> 5;

    if (blockIdx.x < NB_PAIR) {
        // ---------------- pairs ----------------
        const int b     = blockIdx.x >> 3;
        const int slice = blockIdx.x & 7;
        const int len   = __ldg(&seq_lens[b]);
        const float bg  = __ldg(&bg_ptr[0]);

        for (int l = threadIdx.x; l < MAXLEN; l += blockDim.x)
            ts[l] = seq_pads[b * MAXLEN + l];
        __syncthreads();

        double local = 0.0;
        for (int i = slice * 8 + w; i < len; i += 64) {
            const float ti = ts[i];
            float s = 0.0f;
            for (int j = lane; j < i; j += 32)
                s += table_interp(ti - ts[j]);
            #pragma unroll
            for (int o = 16; o > 0; o >>= 1)
                s += __shfl_down_sync(0xffffffffu, s, o);
            if (lane == 0)
                local += (double)logf(bg + s);
        }
        if (lane == 0) wsum[w] = local;
        __syncthreads();
        if (threadIdx.x == 0) {
            double t = 0.0;
            #pragma unroll
            for (int k = 0; k < 8; ++k) t += wsum[k];
            atomicAdd(&g_accum[0], t);
        }
    } else {
        // ---------------- Monte Carlo ----------------
        const int mb = blockIdx.x - NB_PAIR;
        float contrib = 0.0f;
        #pragma unroll
        for (int c = 0; c < 4; ++c) {
            int idx = mb * 1024 + c * 256 + threadIdx.x;   // always < MC_HALF
            uint32_t x0 = (uint32_t)idx;
            uint32_t x1 = (uint32_t)(idx + MC_HALF);
            threefry2x32_key0_42(x0, x1);
            contrib += mc_contrib(idx,           x0, seq_pads, seq_lens);
            contrib += mc_contrib(idx + MC_HALF, x1, seq_pads, seq_lens);
        }
        #pragma unroll
        for (int o = 16; o > 0; o >>= 1)
            contrib += __shfl_down_sync(0xffffffffu, contrib, o);
        if (lane == 0) wsum[w] = (double)contrib;
        __syncthreads();
        if (threadIdx.x == 0) {
            double t = 0.0;
            #pragma unroll
            for (int k = 0; k < 8; ++k) t += wsum[k];
            atomicAdd(&g_accum[1], t);
        }
    }

    // ---------------- arrival + finalize ----------------
    if (threadIdx.x == 0) {
        __threadfence();
        unsigned int old = atomicAdd(&g_arrive, 1u);
        if (old == NB_ALL - 1) {
            double s0 = atomicAdd(&g_accum[0], 0.0);
            double s1 = atomicAdd(&g_accum[1], 0.0);
            double bg = (double)__ldg(&bg_ptr[0]);
            double lamb_ints = s1 / (double)N_MC
                             + (double)BATCH * (double)T_END * bg;
            out[0] = (float)(-(s0 - lamb_ints) / (double)BATCH);
            g_arrive = 0u;                       // reset for next graph replay
        }
    }
}

// ---------------------------------------------------------------------------
// Launch: 2 kernels total
// ---------------------------------------------------------------------------
extern "C" void kernel_launch(void* const* d_in, const int* in_sizes, int n_in,
                              void* d_out, int out_size)
{
    const float* seq  = (const float*)d_in[0];
    const int*   lens = (const int*)  d_in[1];
    const float* bg   = (const float*)d_in[2];
    const float* W1   = (const float*)d_in[3];
    const float* b1   = (const float*)d_in[4];
    const float* W2   = (const float*)d_in[5];
    const float* b2   = (const float*)d_in[6];
    const float* W3   = (const float*)d_in[7];
    const float* b3   = (const float*)d_in[8];
    const float* W4   = (const float*)d_in[9];
    const float* b4   = (const float*)d_in[10];
    float* out = (float*)d_out;

    (void)in_sizes; (void)n_in; (void)out_size;

    const int build_blocks = (G_EXT + 31) / 32;   // 129
    build_table_kernel<<<build_blocks, 256>>>(W1, b1, W2, b2, W3, b3, W4, b4);
    consume_kernel<<<NB_ALL, 256>>>(seq, lens, bg, out);
}

// round 15
// speedup vs baseline: 2.8580x; 1.9680x over previous
#include <cuda_runtime.h>
#include <cuda_bf16.h>
#include <cstdint>

// Problem constants
#define BATCH   16
#define MAXLEN  384
#define HIDDEN  128
#define T_END   100.0f
#define N_MC    15
#define EPS_F   1e-10f

// Table config: value-only table, 4-point Lagrange interpolation.
// Interior grid: G_TABLE points covering [0,100]; one guard point each end.
// Packed as overlapping float4 windows: g_tab4[i] = {f_ext[i..i+3]}.
#define G_TABLE 4096
#define H_STEP  (100.0f / (float)(G_TABLE - 1))
#define INV_H   ((float)(G_TABLE - 1) / 100.0f)
#define G_EXT   (G_TABLE + 2)                  // ext index i -> x = (i-1)*H_STEP
#define G_TAB4  (G_TABLE - 1)                  // valid window starts: 0..G_TABLE-2

// MC RNG layout: 15*16*384 = 92160 uniforms; threefry counter split at half
#define MC_TOTAL 92160
#define MC_HALF  46080

// Fused consume kernel block layout
#define NB_PAIR 128                            // 16 batches x 8 slices
#define NB_MC   45                             // 45*256 threads * 4 counters = 46080
#define NB_ALL  (NB_PAIR + NB_MC)

// ---------------------------------------------------------------------------
// Device scratch (no allocations allowed)
// ---------------------------------------------------------------------------
__device__ float4       g_tab4[G_TAB4];        // overlapping 4-point windows
__device__ double       g_accum[2];            // [0]=sum_log, [1]=mc raw sum
__device__ unsigned int g_arrive;              // arrival ticket (reset by finalizer)

// ---------------------------------------------------------------------------
// Table build: evaluate MLP value on extended grid, fp32.
// Block = 1024 threads (32 warps, 8/SMSP), 32 grid points (lane = point).
// Warp q computes hidden units k in [4q, 4q+4) — exactly one float4 of W
// per j. Activations in smem [j][p]. Head scatter-writes float4 windows.
// ---------------------------------------------------------------------------
__global__ __launch_bounds__(1024) void build_table_kernel(
    const float* __restrict__ W1, const float* __restrict__ b1,
    const float* __restrict__ W2, const float* __restrict__ b2,
    const float* __restrict__ W3, const float* __restrict__ b3,
    const float* __restrict__ W4, const float* __restrict__ b4)
{
    __shared__ float buf[HIDDEN * 32];          // [j][p], 16 KB
    __shared__ float part[32][33];              // head partial sums

    const int lane  = threadIdx.x & 31;
    const int q     = threadIdx.x >> 5;         // warp id 0..31
    const int p     = lane;                     // point index in block
    const int gbase = blockIdx.x * 32;
    const float x   = (float)(gbase + p - 1) * H_STEP;   // ext index -> x

    if (blockIdx.x == 0 && threadIdx.x == 0) {
        g_accum[0] = 0.0;
        g_accum[1] = 0.0;
    }

    // ---- Layer 1: warp q fills j in [4q, 4q+4)
    #pragma unroll
    for (int jj = 0; jj < 4; ++jj) {
        int j = q * 4 + jj;
        float w = __ldg(&W1[j]);
        buf[j * 32 + p] = tanhf(w * x + __ldg(&b1[j]));
    }
    __syncthreads();

    // ---- Layers 2, 3: warp q computes outputs k in [4q, 4q+4)
    const float* Ws[2] = { W2, W3 };
    const float* bs[2] = { b2, b3 };

    #pragma unroll 1
    for (int layer = 0; layer < 2; ++layer) {
        const float* __restrict__ W  = Ws[layer];
        const float* __restrict__ bv = bs[layer];

        const int k0 = q * 4;
        float acc0 = __ldg(&bv[k0 + 0]);
        float acc1 = __ldg(&bv[k0 + 1]);
        float acc2 = __ldg(&bv[k0 + 2]);
        float acc3 = __ldg(&bv[k0 + 3]);

        #pragma unroll 8
        for (int j = 0; j < HIDDEN; ++j) {
            float h = buf[j * 32 + p];
            float4 w0 = __ldg(reinterpret_cast<const float4*>(W + j * HIDDEN + k0));
            acc0 += w0.x * h;
            acc1 += w0.y * h;
            acc2 += w0.z * h;
            acc3 += w0.w * h;
        }

        float rv0 = tanhf(acc0);
        float rv1 = tanhf(acc1);
        float rv2 = tanhf(acc2);
        float rv3 = tanhf(acc3);
        __syncthreads();
        buf[(k0 + 0) * 32 + p] = rv0;
        buf[(k0 + 1) * 32 + p] = rv1;
        buf[(k0 + 2) * 32 + p] = rv2;
        buf[(k0 + 3) * 32 + p] = rv3;
        __syncthreads();
    }

    // ---- Layer 4 + softplus head: warp q sums j in [4q, 4q+4)
    {
        float accv = 0.0f;
        #pragma unroll
        for (int jj = 0; jj < 4; ++jj) {
            int j = q * 4 + jj;
            accv += __ldg(&W4[j]) * buf[j * 32 + p];
        }
        part[q][p] = accv;
    }
    __syncthreads();
    if (q == 0) {
        float z = __ldg(&b4[0]);
        #pragma unroll
        for (int k = 0; k < 32; ++k) z += part[k][p];
        float f = log1pf(expf(-fabsf(z))) + fmaxf(z, 0.0f);   // softplus
        int gi = gbase + p;                                   // ext index
        if (gi < G_EXT) {
            // f = f_ext[gi] belongs to window idx = gi - c at component c
            float* tabf = reinterpret_cast<float*>(g_tab4);
            #pragma unroll
            for (int c = 0; c < 4; ++c) {
                int idx = gi - c;
                if (idx >= 0 && idx < G_TAB4)
                    tabf[idx * 4 + c] = f;
            }
        }
    }
}

// ---------------------------------------------------------------------------
// 4-point cubic Lagrange interpolation, single LDG.128 per lookup
// ---------------------------------------------------------------------------
__device__ __forceinline__ float table_interp(float x)
{
    float pf = x * INV_H;
    pf = fminf(fmaxf(pf, 0.0f), (float)(G_TABLE - 1));
    int g = (int)pf;
    if (g > G_TABLE - 2) g = G_TABLE - 2;
    float u = pf - (float)g;

    float4 f = __ldg(&g_tab4[g]);

    float um1 = u - 1.0f, um2 = u - 2.0f, up1 = u + 1.0f;
    float w0 = -u  * um1 * um2 * (1.0f / 6.0f);
    float w1 = up1 * um1 * um2 * 0.5f;
    float w2 = -up1 * u  * um2 * 0.5f;
    float w3 = up1 * u  * um1 * (1.0f / 6.0f);
    return w0 * f.x + w1 * f.y + w2 * f.z + w3 * f.w;
}

// ---------------------------------------------------------------------------
// Threefry-2x32 (JAX-compatible), key = (0, 42)
// ---------------------------------------------------------------------------
__device__ __forceinline__ uint32_t rotl32(uint32_t v, int s)
{
    return __funnelshift_l(v, v, s);
}

__device__ __forceinline__ void tf_round4(uint32_t& x0, uint32_t& x1,
                                          int a, int b, int c, int d)
{
    x0 += x1; x1 = rotl32(x1, a); x1 ^= x0;
    x0 += x1; x1 = rotl32(x1, b); x1 ^= x0;
    x0 += x1; x1 = rotl32(x1, c); x1 ^= x0;
    x0 += x1; x1 = rotl32(x1, d); x1 ^= x0;
}

__device__ __forceinline__ void threefry2x32_key0_42(uint32_t& x0, uint32_t& x1)
{
    const uint32_t ks0 = 0u;
    const uint32_t ks1 = 42u;
    const uint32_t ks2 = 0x1BD11BDAu ^ 42u;
    x0 += ks0; x1 += ks1;
    tf_round4(x0, x1, 13, 15, 26, 6);
    x0 += ks1; x1 += ks2 + 1u;
    tf_round4(x0, x1, 17, 29, 16, 24);
    x0 += ks2; x1 += ks0 + 2u;
    tf_round4(x0, x1, 13, 15, 26, 6);
    x0 += ks0; x1 += ks1 + 3u;
    tf_round4(x0, x1, 17, 29, 16, 24);
    x0 += ks1; x1 += ks2 + 4u;
    tf_round4(x0, x1, 13, 15, 26, 6);
    x0 += ks2; x1 += ks0 + 5u;
}

__device__ __forceinline__ float mc_contrib(int flat, uint32_t bits,
                                            const float* __restrict__ seq,
                                            const int* __restrict__ lens)
{
    const int l = flat % MAXLEN;
    const int b = (flat / MAXLEN) % BATCH;
    if (l >= __ldg(&lens[b])) return 0.0f;       // diff_last == 0
    float u = __uint_as_float((bits >> 9) | 0x3f800000u) - 1.0f;
    float t = __ldg(&seq[b * MAXLEN + l]);
    float diff = T_END - t;
    float f = table_interp(u * diff);
    return (f + EPS_F) * diff;
}

// ---------------------------------------------------------------------------
// Fused consume kernel:
//   blocks [0, NB_PAIR): pair-sum log term for batch b = blk>>3, slice blk&7
//   blocks [NB_PAIR, NB_ALL): Monte-Carlo integral term
//   last-arriving block writes the final NLL.
// ---------------------------------------------------------------------------
__global__ __launch_bounds__(256) void consume_kernel(
    const float* __restrict__ seq_pads,
    const int*   __restrict__ seq_lens,
    const float* __restrict__ bg_ptr,
    float*       __restrict__ out)
{
    __shared__ float  ts[MAXLEN];
    __shared__ double wsum[8];

    const int lane = threadIdx.x & 31;
    const int w    = threadIdx.x >> 5;

    if (blockIdx.x < NB_PAIR) {
        // ---------------- pairs ----------------
        const int b     = blockIdx.x >> 3;
        const int slice = blockIdx.x & 7;
        const int len   = __ldg(&seq_lens[b]);
        const float bg  = __ldg(&bg_ptr[0]);

        for (int l = threadIdx.x; l < MAXLEN; l += blockDim.x)
            ts[l] = seq_pads[b * MAXLEN + l];
        __syncthreads();

        double local = 0.0;
        for (int i = slice * 8 + w; i < len; i += 64) {
            const float ti = ts[i];
            float s = 0.0f;
            for (int j = lane; j < i; j += 32)
                s += table_interp(ti - ts[j]);
            #pragma unroll
            for (int o = 16; o > 0; o >>= 1)
                s += __shfl_down_sync(0xffffffffu, s, o);
            if (lane == 0)
                local += (double)logf(bg + s);
        }
        if (lane == 0) wsum[w] = local;
        __syncthreads();
        if (threadIdx.x == 0) {
            double t = 0.0;
            #pragma unroll
            for (int k = 0; k < 8; ++k) t += wsum[k];
            atomicAdd(&g_accum[0], t);
        }
    } else {
        // ---------------- Monte Carlo ----------------
        const int mb = blockIdx.x - NB_PAIR;
        float contrib = 0.0f;
        #pragma unroll
        for (int c = 0; c < 4; ++c) {
            int idx = mb * 1024 + c * 256 + threadIdx.x;   // always < MC_HALF
            uint32_t x0 = (uint32_t)idx;
            uint32_t x1 = (uint32_t)(idx + MC_HALF);
            threefry2x32_key0_42(x0, x1);
            contrib += mc_contrib(idx,           x0, seq_pads, seq_lens);
            contrib += mc_contrib(idx + MC_HALF, x1, seq_pads, seq_lens);
        }
        #pragma unroll
        for (int o = 16; o > 0; o >>= 1)
            contrib += __shfl_down_sync(0xffffffffu, contrib, o);
        if (lane == 0) wsum[w] = (double)contrib;
        __syncthreads();
        if (threadIdx.x == 0) {
            double t = 0.0;
            #pragma unroll
            for (int k = 0; k < 8; ++k) t += wsum[k];
            atomicAdd(&g_accum[1], t);
        }
    }

    // ---------------- arrival + finalize ----------------
    if (threadIdx.x == 0) {
        __threadfence();
        unsigned int old = atomicAdd(&g_arrive, 1u);
        if (old == NB_ALL - 1) {
            double s0 = atomicAdd(&g_accum[0], 0.0);
            double s1 = atomicAdd(&g_accum[1], 0.0);
            double bg = (double)__ldg(&bg_ptr[0]);
            double lamb_ints = s1 / (double)N_MC
                             + (double)BATCH * (double)T_END * bg;
            out[0] = (float)(-(s0 - lamb_ints) / (double)BATCH);
            g_arrive = 0u;                       // reset for next graph replay
        }
    }
}

// ---------------------------------------------------------------------------
// Launch: 2 kernels total
// ---------------------------------------------------------------------------
extern "C" void kernel_launch(void* const* d_in, const int* in_sizes, int n_in,
                              void* d_out, int out_size)
{
    const float* seq  = (const float*)d_in[0];
    const int*   lens = (const int*)  d_in[1];
    const float* bg   = (const float*)d_in[2];
    const float* W1   = (const float*)d_in[3];
    const float* b1   = (const float*)d_in[4];
    const float* W2   = (const float*)d_in[5];
    const float* b2   = (const float*)d_in[6];
    const float* W3   = (const float*)d_in[7];
    const float* b3   = (const float*)d_in[8];
    const float* W4   = (const float*)d_in[9];
    const float* b4   = (const float*)d_in[10];
    float* out = (float*)d_out;

    (void)in_sizes; (void)n_in; (void)out_size;

    const int build_blocks = (G_EXT + 31) / 32;   // 129
    build_table_kernel<<<build_blocks, 1024>>>(W1, b1, W2, b2, W3, b3, W4, b4);
    consume_kernel<<<NB_ALL, 256>>>(seq, lens, bg, out);
}